// round 6
// baseline (speedup 1.0000x reference)
#include <cuda_runtime.h>
#include <cuda_bf16.h>
#include <math.h>

// Problem constants
#define SEQ   2048
#define DMODEL 4096
#define NHEAD 32
#define NKVH  8
#define HDIM  128
#define NREP  4          // NHEAD / NKVH

// ---------------------------------------------------------------------------
// Scratch (device globals; no allocation allowed)
// ---------------------------------------------------------------------------
__device__ float g_q[SEQ * DMODEL];          // (s, h, d) = s*4096 + h*128 + d
__device__ float g_k[SEQ * NKVH * HDIM];     // (s, kvh, d)
__device__ float g_v[SEQ * NKVH * HDIM];
__device__ float g_att[SEQ * DMODEL];        // attention output (s, h*128+d)

// ---------------------------------------------------------------------------
// Generic tiled FP32 GEMM:  C[M,N] = A[M,K] @ B[K,N]   (all row-major)
// BM=BN=128, BK=8, 256 threads, 8x8 per thread.
// ---------------------------------------------------------------------------
#define GBM 128
#define GBN 128
#define GBK 8

__global__ __launch_bounds__(256, 2)
void gemm_nn(const float* __restrict__ A, const float* __restrict__ B,
             float* __restrict__ C, int M, int N, int K)
{
    __shared__ float As[GBK * GBM];   // transposed: As[k][m]
    __shared__ float Bs[GBK * GBN];   // natural:    Bs[k][n]

    const int tid = threadIdx.x;
    const int bm = blockIdx.y * GBM;
    const int bn = blockIdx.x * GBN;
    const int tx = tid & 15;
    const int ty = tid >> 4;

    // global load assignments
    const int a_row = tid >> 1;            // 0..127
    const int a_c4  = (tid & 1) * 4;       // 0 or 4
    const int b_row = tid >> 5;            // 0..7
    const int b_c4  = (tid & 31) * 4;      // 0..124

    float acc[8][8];
#pragma unroll
    for (int i = 0; i < 8; i++)
#pragma unroll
        for (int j = 0; j < 8; j++) acc[i][j] = 0.f;

    for (int k0 = 0; k0 < K; k0 += GBK) {
        float4 av = *(const float4*)&A[(size_t)(bm + a_row) * K + k0 + a_c4];
        float4 bv = *(const float4*)&B[(size_t)(k0 + b_row) * N + bn + b_c4];
        __syncthreads();
        As[(a_c4 + 0) * GBM + a_row] = av.x;
        As[(a_c4 + 1) * GBM + a_row] = av.y;
        As[(a_c4 + 2) * GBM + a_row] = av.z;
        As[(a_c4 + 3) * GBM + a_row] = av.w;
        *(float4*)&Bs[b_row * GBN + b_c4] = bv;
        __syncthreads();

#pragma unroll
        for (int k = 0; k < GBK; k++) {
            float4 A0 = *(float4*)&As[k * GBM + ty * 8];
            float4 A1 = *(float4*)&As[k * GBM + ty * 8 + 4];
            float4 B0 = *(float4*)&Bs[k * GBN + tx * 4];
            float4 B1 = *(float4*)&Bs[k * GBN + 64 + tx * 4];
            float a[8] = {A0.x, A0.y, A0.z, A0.w, A1.x, A1.y, A1.z, A1.w};
            float b[8] = {B0.x, B0.y, B0.z, B0.w, B1.x, B1.y, B1.z, B1.w};
#pragma unroll
            for (int i = 0; i < 8; i++)
#pragma unroll
                for (int j = 0; j < 8; j++)
                    acc[i][j] = fmaf(a[i], b[j], acc[i][j]);
        }
    }

#pragma unroll
    for (int i = 0; i < 8; i++) {
        const size_t row = (size_t)(bm + ty * 8 + i) * N;
        *(float4*)&C[row + bn + tx * 4]      = make_float4(acc[i][0], acc[i][1], acc[i][2], acc[i][3]);
        *(float4*)&C[row + bn + 64 + tx * 4] = make_float4(acc[i][4], acc[i][5], acc[i][6], acc[i][7]);
    }
}

// ---------------------------------------------------------------------------
// RoPE on Q and K in place.
// ---------------------------------------------------------------------------
__global__ void rope_kernel(const float* __restrict__ cosb, const float* __restrict__ sinb)
{
    const int NQ = SEQ * NHEAD * (HDIM / 2);
    const int NK = SEQ * NKVH * (HDIM / 2);
    int idx = blockIdx.x * blockDim.x + threadIdx.x;
    if (idx < NQ) {
        int s = idx / (NHEAD * 64);
        int r = idx % (NHEAD * 64);
        int h = r / 64, i = r % 64;
        float c = cosb[s * 64 + i], sn = sinb[s * 64 + i];
        float* p = &g_q[(size_t)s * DMODEL + h * HDIM + 2 * i];
        float te = p[0], to = p[1];
        p[0] = te * c - to * sn;
        p[1] = to * c + te * sn;
    } else if (idx < NQ + NK) {
        int j = idx - NQ;
        int s = j / (NKVH * 64);
        int r = j % (NKVH * 64);
        int h = r / 64, i = r % 64;
        float c = cosb[s * 64 + i], sn = sinb[s * 64 + i];
        float* p = &g_k[(size_t)s * (NKVH * HDIM) + h * HDIM + 2 * i];
        float te = p[0], to = p[1];
        p[0] = te * c - to * sn;
        p[1] = to * c + te * sn;
    }
}

// ---------------------------------------------------------------------------
// Simple, transparently-correct attention: one warp per (query row, head).
// Lane owns head-dims [4*lane, 4*lane+3]. Online softmax in registers.
// Causal handled by loop bound (k <= q) — no mask constants.
//
// GQA mapping per the reference's _repeat_kv:
//   repeat(t[:, :, None, :, :], n_rep, axis=2).reshape(..., n_rep*n_kv, hd)
//   => head h uses kv head (h % NKVH), NOT h / NREP.
// ---------------------------------------------------------------------------
__global__ __launch_bounds__(256)
void attn_simple()
{
    const int h    = blockIdx.y;
    const int kvh  = h & (NKVH - 1);            // h % 8  (see note above)
    const int warp = threadIdx.x >> 5;
    const int lane = threadIdx.x & 31;
    const int q    = blockIdx.x * 8 + warp;
    const float scale = 0.08838834764831845f;   // 1/sqrt(128)

    const float* __restrict__ Kbase = g_k + kvh * HDIM + lane * 4;
    const float* __restrict__ Vbase = g_v + kvh * HDIM + lane * 4;

    float4 q4 = *(const float4*)&g_q[(size_t)q * DMODEL + h * HDIM + lane * 4];
    q4.x *= scale; q4.y *= scale; q4.z *= scale; q4.w *= scale;

    float m = -INFINITY, l = 0.f;
    float4 o = make_float4(0.f, 0.f, 0.f, 0.f);

    for (int k = 0; k <= q; k++) {
        float4 k4 = *(const float4*)&Kbase[(size_t)k * (NKVH * HDIM)];
        float s = q4.x * k4.x + q4.y * k4.y + q4.z * k4.z + q4.w * k4.w;
        s += __shfl_xor_sync(0xffffffffu, s, 16);
        s += __shfl_xor_sync(0xffffffffu, s, 8);
        s += __shfl_xor_sync(0xffffffffu, s, 4);
        s += __shfl_xor_sync(0xffffffffu, s, 2);
        s += __shfl_xor_sync(0xffffffffu, s, 1);

        float mn    = fmaxf(m, s);
        float alpha = __expf(m - mn);
        float p     = __expf(s - mn);

        float4 v4 = *(const float4*)&Vbase[(size_t)k * (NKVH * HDIM)];
        o.x = o.x * alpha + p * v4.x;
        o.y = o.y * alpha + p * v4.y;
        o.z = o.z * alpha + p * v4.z;
        o.w = o.w * alpha + p * v4.w;
        l = l * alpha + p;
        m = mn;
    }

    const float inv = 1.f / l;
    o.x *= inv; o.y *= inv; o.z *= inv; o.w *= inv;
    *(float4*)&g_att[(size_t)q * DMODEL + h * HDIM + lane * 4] = o;
}

// ---------------------------------------------------------------------------
// Launch
// ---------------------------------------------------------------------------
extern "C" void kernel_launch(void* const* d_in, const int* in_sizes, int n_in,
                              void* d_out, int out_size)
{
    const float* x    = (const float*)d_in[0];
    const float* wq   = (const float*)d_in[1];
    const float* wk   = (const float*)d_in[2];
    const float* wv   = (const float*)d_in[3];
    const float* wo   = (const float*)d_in[4];
    const float* fcos = (const float*)d_in[5];
    const float* fsin = (const float*)d_in[6];
    float* out = (float*)d_out;

    float *gq, *gk, *gv, *ga;
    cudaGetSymbolAddress((void**)&gq, g_q);
    cudaGetSymbolAddress((void**)&gk, g_k);
    cudaGetSymbolAddress((void**)&gv, g_v);
    cudaGetSymbolAddress((void**)&ga, g_att);

    // QKV projections
    gemm_nn<<<dim3(DMODEL / GBN, SEQ / GBM), 256>>>(x, wq, gq, SEQ, DMODEL, DMODEL);
    gemm_nn<<<dim3((NKVH * HDIM) / GBN, SEQ / GBM), 256>>>(x, wk, gk, SEQ, NKVH * HDIM, DMODEL);
    gemm_nn<<<dim3((NKVH * HDIM) / GBN, SEQ / GBM), 256>>>(x, wv, gv, SEQ, NKVH * HDIM, DMODEL);

    // RoPE (Q then K)
    {
        int np = SEQ * (NHEAD + NKVH) * (HDIM / 2);
        rope_kernel<<<(np + 255) / 256, 256>>>(fcos, fsin);
    }

    // Attention: one warp per (q, h); grid (SEQ/8, NHEAD)
    attn_simple<<<dim3(SEQ / 8, NHEAD), 256>>>();

    // Output projection -> d_out
    gemm_nn<<<dim3(DMODEL / GBN, SEQ / GBM), 256>>>(ga, wo, out, SEQ, DMODEL, DMODEL);
}

// round 11
// speedup vs baseline: 1.5055x; 1.5055x over previous
#include <cuda_runtime.h>
#include <cuda_bf16.h>
#include <math.h>
#include <stdint.h>

// Problem constants
#define SEQ    2048
#define DMODEL 4096
#define NHEAD  32
#define NKVH   8
#define HDIM   128

// ---------------------------------------------------------------------------
// Helpers
// ---------------------------------------------------------------------------
__device__ __forceinline__ uint32_t smem_u32(const void* p) {
    uint32_t a;
    asm("{ .reg .u64 t; cvta.to.shared.u64 t, %1; cvt.u32.u64 %0, t; }" : "=r"(a) : "l"(p));
    return a;
}
__device__ __forceinline__ void ldsm_x4(uint32_t* r, uint32_t addr) {
    asm volatile("ldmatrix.sync.aligned.m8n8.x4.shared.b16 {%0,%1,%2,%3}, [%4];"
                 : "=r"(r[0]), "=r"(r[1]), "=r"(r[2]), "=r"(r[3]) : "r"(addr));
}
__device__ __forceinline__ void mma16816(float* c, const uint32_t* a, const uint32_t* b) {
    asm volatile("mma.sync.aligned.m16n8k16.row.col.f32.bf16.bf16.f32 "
                 "{%0,%1,%2,%3}, {%4,%5,%6,%7}, {%8,%9}, {%0,%1,%2,%3};"
                 : "+f"(c[0]), "+f"(c[1]), "+f"(c[2]), "+f"(c[3])
                 : "r"(a[0]), "r"(a[1]), "r"(a[2]), "r"(a[3]), "r"(b[0]), "r"(b[1]));
}
__device__ __forceinline__ void cp16(uint32_t dst, const void* src) {
    asm volatile("cp.async.cg.shared.global [%0], [%1], 16;" :: "r"(dst), "l"(src));
}

// ---------------------------------------------------------------------------
// Scratch (device globals; no allocation allowed)
// ---------------------------------------------------------------------------
__device__ float g_q[SEQ * DMODEL];
__device__ float g_k[SEQ * NKVH * HDIM];
__device__ float g_v[SEQ * NKVH * HDIM];

__device__ __nv_bfloat16 a_hi[SEQ * DMODEL], a_lo[SEQ * DMODEL];       // x split
__device__ __nv_bfloat16 att_hi[SEQ * DMODEL], att_lo[SEQ * DMODEL];   // attention out split
__device__ __nv_bfloat16 wqT_h[DMODEL * DMODEL], wqT_l[DMODEL * DMODEL];
__device__ __nv_bfloat16 wkT_h[1024 * DMODEL],  wkT_l[1024 * DMODEL];
__device__ __nv_bfloat16 wvT_h[1024 * DMODEL],  wvT_l[1024 * DMODEL];
__device__ __nv_bfloat16 woT_h[DMODEL * DMODEL], woT_l[DMODEL * DMODEL];

// ---------------------------------------------------------------------------
// Elementwise fp32 -> bf16 hi/lo split of x
// ---------------------------------------------------------------------------
__global__ void convert_x(const float* __restrict__ x)
{
    int i = blockIdx.x * blockDim.x + threadIdx.x;   // < 2M
    float4 v = *(const float4*)&x[(size_t)i * 4];
    float f[4] = {v.x, v.y, v.z, v.w};
#pragma unroll
    for (int j = 0; j < 4; j++) {
        __nv_bfloat16 h = __float2bfloat16(f[j]);
        __nv_bfloat16 l = __float2bfloat16(f[j] - __bfloat162float(h));
        a_hi[(size_t)i * 4 + j] = h;
        a_lo[(size_t)i * 4 + j] = l;
    }
}

// ---------------------------------------------------------------------------
// Transpose+split a weight:  w[K=4096, N] fp32  ->  wT[N, 4096] bf16 hi/lo
// ---------------------------------------------------------------------------
__global__ void transpose_w(const float* __restrict__ w,
                            __nv_bfloat16* __restrict__ oh,
                            __nv_bfloat16* __restrict__ ol, int N)
{
    __shared__ float t[32][33];
    const int tx = threadIdx.x, ty = threadIdx.y;
    const int n0 = blockIdx.x * 32, k0 = blockIdx.y * 32;
#pragma unroll
    for (int i = 0; i < 4; i++)
        t[ty + 8 * i][tx] = w[(size_t)(k0 + ty + 8 * i) * N + n0 + tx];
    __syncthreads();
#pragma unroll
    for (int i = 0; i < 4; i++) {
        float v = t[tx][ty + 8 * i];
        __nv_bfloat16 h = __float2bfloat16(v);
        __nv_bfloat16 l = __float2bfloat16(v - __bfloat162float(h));
        size_t off = (size_t)(n0 + ty + 8 * i) * DMODEL + k0 + tx;
        oh[off] = h;
        ol[off] = l;
    }
}

// ---------------------------------------------------------------------------
// bf16-split HMMA GEMM:  C[2048, N] = A[2048, 4096] @ B[4096, N]
//   A: hi/lo bf16 [M,4096] row-major.  B: TRANSPOSED hi/lo bf16 [N,4096]
//   (rows of BT are columns of B => exactly the col-major B that
//    mma.sync ... .row.col expects, loaded with non-trans ldmatrix).
//   Block 128x128, 8 warps (4m x 2n), warp tile 32x64, K-chunk 32.
//   Split: C = Ah*Bh + Ah*Bl + Al*Bh  (fp32 accumulate).
//   Smem rows padded to 80 B -> conflict-free ldmatrix.
// ---------------------------------------------------------------------------
#define OP_BYTES  (128 * 80)                  // one operand tile per stage
#define STAGE_BYTES (4 * OP_BYTES)            // Ah | Al | Bh | Bl
#define GH_SMEM   (2 * STAGE_BYTES)           // double buffered (81920 B)

__global__ __launch_bounds__(256)
void gemm_hmma(const __nv_bfloat16* __restrict__ Ah, const __nv_bfloat16* __restrict__ Al,
               const __nv_bfloat16* __restrict__ BhT, const __nv_bfloat16* __restrict__ BlT,
               float* __restrict__ C, int N)
{
    extern __shared__ char smem_raw[];
    const uint32_t sb = smem_u32(smem_raw);
    const int tid  = threadIdx.x;
    const int wid  = tid >> 5;
    const int lane = tid & 31;
    const int wr   = wid & 3;        // warp m index (0..3)
    const int wc   = wid >> 2;       // warp n index (0..1)
    const int m0 = blockIdx.y * 128, n0 = blockIdx.x * 128;

    const __nv_bfloat16* gAh = Ah  + (size_t)m0 * DMODEL;
    const __nv_bfloat16* gAl = Al  + (size_t)m0 * DMODEL;
    const __nv_bfloat16* gBh = BhT + (size_t)n0 * DMODEL;
    const __nv_bfloat16* gBl = BlT + (size_t)n0 * DMODEL;

    // staging: 4 operands x 128 rows x (32 bf16 = 4 x 16B segs); 2 segs/thread/operand
    auto stage = [&](int c, int s) {
        const uint32_t base = sb + s * STAGE_BYTES;
        const int koff = c * 32;
#pragma unroll
        for (int t = 0; t < 2; t++) {
            int seg = tid + t * 256;          // 0..511
            int row = seg >> 2, c16 = seg & 3;
            uint32_t so = row * 80 + c16 * 16;
            size_t   go = (size_t)row * DMODEL + koff + c16 * 8;
            cp16(base + so,                gAh + go);
            cp16(base + OP_BYTES + so,     gAl + go);
            cp16(base + 2 * OP_BYTES + so, gBh + go);
            cp16(base + 3 * OP_BYTES + so, gBl + go);
        }
        asm volatile("cp.async.commit_group;");
    };

    float acc[2][8][4];
#pragma unroll
    for (int i = 0; i < 2; i++)
#pragma unroll
        for (int j = 0; j < 8; j++)
#pragma unroll
            for (int q = 0; q < 4; q++) acc[i][j][q] = 0.f;

    // per-lane ldmatrix offsets (byte offsets within an operand tile)
    const int mb = wr * 32;
    const uint32_t a_off = (mb + (lane & 15)) * 80 + ((lane >> 4) << 3) * 2;
    const uint32_t b_off = ((wc * 64) + (lane & 7) + ((lane >> 4) << 3)) * 80
                         + (((lane >> 3) & 1) << 3) * 2;

    stage(0, 0);
    const int NCH = DMODEL / 32;     // 128
    for (int c = 0; c < NCH; c++) {
        const int s = c & 1;
        if (c + 1 < NCH) {
            stage(c + 1, s ^ 1);
            asm volatile("cp.async.wait_group 1;");
        } else {
            asm volatile("cp.async.wait_group 0;");
        }
        __syncthreads();

        const uint32_t tAh = sb + s * STAGE_BYTES;
        const uint32_t tAl = tAh + OP_BYTES;
        const uint32_t tBh = tAh + 2 * OP_BYTES;
        const uint32_t tBl = tAh + 3 * OP_BYTES;

#pragma unroll
        for (int ks = 0; ks < 2; ks++) {
            const uint32_t kb = ks * 32;     // 16 bf16 = 32 bytes
#pragma unroll
            for (int pass = 0; pass < 3; pass++) {
                const uint32_t ta = (pass == 2) ? tAl : tAh;
                const uint32_t tb = (pass == 1) ? tBl : tBh;
                uint32_t a[2][4], b[4][4];
                ldsm_x4(a[0], ta + a_off + kb);
                ldsm_x4(a[1], ta + a_off + kb + 16 * 80);
#pragma unroll
                for (int q = 0; q < 4; q++)
                    ldsm_x4(b[q], tb + b_off + kb + q * 16 * 80);
#pragma unroll
                for (int i = 0; i < 2; i++)
#pragma unroll
                    for (int q = 0; q < 4; q++) {
                        mma16816(acc[i][2 * q],     a[i], &b[q][0]);
                        mma16816(acc[i][2 * q + 1], a[i], &b[q][2]);
                    }
            }
        }
        __syncthreads();
    }

    // epilogue: fragment -> global fp32
    const int rbase = m0 + wr * 32 + (lane >> 2);
    const int cbase = n0 + wc * 64 + 2 * (lane & 3);
#pragma unroll
    for (int i = 0; i < 2; i++)
#pragma unroll
        for (int j = 0; j < 8; j++) {
            int r = rbase + i * 16;
            int cc = cbase + j * 8;
            *(float2*)&C[(size_t)r * N + cc]       = make_float2(acc[i][j][0], acc[i][j][1]);
            *(float2*)&C[(size_t)(r + 8) * N + cc] = make_float2(acc[i][j][2], acc[i][j][3]);
        }
}

// ---------------------------------------------------------------------------
// RoPE on Q and K in place (fp32).
// ---------------------------------------------------------------------------
__global__ void rope_kernel(const float* __restrict__ cosb, const float* __restrict__ sinb)
{
    const int NQ = SEQ * NHEAD * (HDIM / 2);
    const int NK = SEQ * NKVH * (HDIM / 2);
    int idx = blockIdx.x * blockDim.x + threadIdx.x;
    if (idx < NQ) {
        int s = idx / (NHEAD * 64);
        int r = idx % (NHEAD * 64);
        int h = r / 64, i = r % 64;
        float c = cosb[s * 64 + i], sn = sinb[s * 64 + i];
        float* p = &g_q[(size_t)s * DMODEL + h * HDIM + 2 * i];
        float te = p[0], to = p[1];
        p[0] = te * c - to * sn;
        p[1] = to * c + te * sn;
    } else if (idx < NQ + NK) {
        int j = idx - NQ;
        int s = j / (NKVH * 64);
        int r = j % (NKVH * 64);
        int h = r / 64, i = r % 64;
        float c = cosb[s * 64 + i], sn = sinb[s * 64 + i];
        float* p = &g_k[(size_t)s * (NKVH * HDIM) + h * HDIM + 2 * i];
        float te = p[0], to = p[1];
        p[0] = te * c - to * sn;
        p[1] = to * c + te * sn;
    }
}

// ---------------------------------------------------------------------------
// Attention: one warp per (q, h); lane owns 4 head dims. Online softmax.
// GQA mapping (reference's _repeat_kv): head h uses kv head (h % 8).
// Epilogue writes bf16 hi/lo split directly (feeds the HMMA O-projection).
// ---------------------------------------------------------------------------
__global__ __launch_bounds__(256)
void attn_simple()
{
    const int h    = blockIdx.y;
    const int kvh  = h & (NKVH - 1);
    const int warp = threadIdx.x >> 5;
    const int lane = threadIdx.x & 31;
    const int q    = blockIdx.x * 8 + warp;
    const float scale = 0.08838834764831845f;   // 1/sqrt(128)

    const float* __restrict__ Kbase = g_k + kvh * HDIM + lane * 4;
    const float* __restrict__ Vbase = g_v + kvh * HDIM + lane * 4;

    float4 q4 = *(const float4*)&g_q[(size_t)q * DMODEL + h * HDIM + lane * 4];
    q4.x *= scale; q4.y *= scale; q4.z *= scale; q4.w *= scale;

    float m = -INFINITY, l = 0.f;
    float4 o = make_float4(0.f, 0.f, 0.f, 0.f);

    for (int k = 0; k <= q; k++) {
        float4 k4 = *(const float4*)&Kbase[(size_t)k * (NKVH * HDIM)];
        float s = q4.x * k4.x + q4.y * k4.y + q4.z * k4.z + q4.w * k4.w;
        s += __shfl_xor_sync(0xffffffffu, s, 16);
        s += __shfl_xor_sync(0xffffffffu, s, 8);
        s += __shfl_xor_sync(0xffffffffu, s, 4);
        s += __shfl_xor_sync(0xffffffffu, s, 2);
        s += __shfl_xor_sync(0xffffffffu, s, 1);

        float mn    = fmaxf(m, s);
        float alpha = __expf(m - mn);
        float p     = __expf(s - mn);

        float4 v4 = *(const float4*)&Vbase[(size_t)k * (NKVH * HDIM)];
        o.x = o.x * alpha + p * v4.x;
        o.y = o.y * alpha + p * v4.y;
        o.z = o.z * alpha + p * v4.z;
        o.w = o.w * alpha + p * v4.w;
        l = l * alpha + p;
        m = mn;
    }

    const float inv = 1.f / l;
    float vals[4] = {o.x * inv, o.y * inv, o.z * inv, o.w * inv};
    size_t base = (size_t)q * DMODEL + h * HDIM + lane * 4;
#pragma unroll
    for (int j = 0; j < 4; j++) {
        __nv_bfloat16 hi = __float2bfloat16(vals[j]);
        __nv_bfloat16 lo = __float2bfloat16(vals[j] - __bfloat162float(hi));
        att_hi[base + j] = hi;
        att_lo[base + j] = lo;
    }
}

// ---------------------------------------------------------------------------
// Launch
// ---------------------------------------------------------------------------
extern "C" void kernel_launch(void* const* d_in, const int* in_sizes, int n_in,
                              void* d_out, int out_size)
{
    const float* x    = (const float*)d_in[0];
    const float* wq   = (const float*)d_in[1];
    const float* wk   = (const float*)d_in[2];
    const float* wv   = (const float*)d_in[3];
    const float* wo   = (const float*)d_in[4];
    const float* fcos = (const float*)d_in[5];
    const float* fsin = (const float*)d_in[6];
    float* out = (float*)d_out;

    float *gq, *gk, *gv;
    cudaGetSymbolAddress((void**)&gq, g_q);
    cudaGetSymbolAddress((void**)&gk, g_k);
    cudaGetSymbolAddress((void**)&gv, g_v);
    __nv_bfloat16 *pah, *pal, *path, *patl;
    __nv_bfloat16 *pwqh, *pwql, *pwkh, *pwkl, *pwvh, *pwvl, *pwoh, *pwol;
    cudaGetSymbolAddress((void**)&pah, a_hi);
    cudaGetSymbolAddress((void**)&pal, a_lo);
    cudaGetSymbolAddress((void**)&path, att_hi);
    cudaGetSymbolAddress((void**)&patl, att_lo);
    cudaGetSymbolAddress((void**)&pwqh, wqT_h);
    cudaGetSymbolAddress((void**)&pwql, wqT_l);
    cudaGetSymbolAddress((void**)&pwkh, wkT_h);
    cudaGetSymbolAddress((void**)&pwkl, wkT_l);
    cudaGetSymbolAddress((void**)&pwvh, wvT_h);
    cudaGetSymbolAddress((void**)&pwvl, wvT_l);
    cudaGetSymbolAddress((void**)&pwoh, woT_h);
    cudaGetSymbolAddress((void**)&pwol, woT_l);

    cudaFuncSetAttribute(gemm_hmma, cudaFuncAttributeMaxDynamicSharedMemorySize, GH_SMEM);

    // Split x; transpose+split weights
    convert_x<<<(SEQ * DMODEL / 4) / 256, 256>>>(x);
    transpose_w<<<dim3(DMODEL / 32, DMODEL / 32), dim3(32, 8)>>>(wq, pwqh, pwql, DMODEL);
    transpose_w<<<dim3(1024 / 32, DMODEL / 32), dim3(32, 8)>>>(wk, pwkh, pwkl, 1024);
    transpose_w<<<dim3(1024 / 32, DMODEL / 32), dim3(32, 8)>>>(wv, pwvh, pwvl, 1024);
    transpose_w<<<dim3(DMODEL / 32, DMODEL / 32), dim3(32, 8)>>>(wo, pwoh, pwol, DMODEL);

    // QKV projections (HMMA)
    gemm_hmma<<<dim3(DMODEL / 128, SEQ / 128), 256, GH_SMEM>>>(pah, pal, pwqh, pwql, gq, DMODEL);
    gemm_hmma<<<dim3(1024 / 128, SEQ / 128), 256, GH_SMEM>>>(pah, pal, pwkh, pwkl, gk, 1024);
    gemm_hmma<<<dim3(1024 / 128, SEQ / 128), 256, GH_SMEM>>>(pah, pal, pwvh, pwvl, gv, 1024);

    // RoPE
    {
        int np = SEQ * (NHEAD + NKVH) * (HDIM / 2);
        rope_kernel<<<(np + 255) / 256, 256>>>(fcos, fsin);
    }

    // Attention (writes att hi/lo)
    attn_simple<<<dim3(SEQ / 8, NHEAD), 256>>>();

    // Output projection (HMMA) -> d_out
    gemm_hmma<<<dim3(DMODEL / 128, SEQ / 128), 256, GH_SMEM>>>(path, patl, pwoh, pwol, out, DMODEL);
}

// round 14
// speedup vs baseline: 3.6572x; 2.4292x over previous
#include <cuda_runtime.h>
#include <cuda_bf16.h>
#include <cuda_fp16.h>
#include <math.h>
#include <stdint.h>

// Problem constants
#define SEQ    2048
#define DMODEL 4096
#define NHEAD  32
#define NKVH   8
#define HDIM   128

// ---------------------------------------------------------------------------
// Helpers
// ---------------------------------------------------------------------------
__device__ __forceinline__ uint32_t smem_u32(const void* p) {
    uint32_t a;
    asm("{ .reg .u64 t; cvta.to.shared.u64 t, %1; cvt.u32.u64 %0, t; }" : "=r"(a) : "l"(p));
    return a;
}
__device__ __forceinline__ void ldsm_x4(uint32_t* r, uint32_t addr) {
    asm volatile("ldmatrix.sync.aligned.m8n8.x4.shared.b16 {%0,%1,%2,%3}, [%4];"
                 : "=r"(r[0]), "=r"(r[1]), "=r"(r[2]), "=r"(r[3]) : "r"(addr));
}
__device__ __forceinline__ void ldsm_x4_t(uint32_t* r, uint32_t addr) {
    asm volatile("ldmatrix.sync.aligned.m8n8.x4.trans.shared.b16 {%0,%1,%2,%3}, [%4];"
                 : "=r"(r[0]), "=r"(r[1]), "=r"(r[2]), "=r"(r[3]) : "r"(addr));
}
__device__ __forceinline__ void mma16816(float* c, const uint32_t* a, const uint32_t* b) {
    asm volatile("mma.sync.aligned.m16n8k16.row.col.f32.bf16.bf16.f32 "
                 "{%0,%1,%2,%3}, {%4,%5,%6,%7}, {%8,%9}, {%0,%1,%2,%3};"
                 : "+f"(c[0]), "+f"(c[1]), "+f"(c[2]), "+f"(c[3])
                 : "r"(a[0]), "r"(a[1]), "r"(a[2]), "r"(a[3]), "r"(b[0]), "r"(b[1]));
}
__device__ __forceinline__ void mma16816h(float* c, const uint32_t* a, const uint32_t* b) {
    asm volatile("mma.sync.aligned.m16n8k16.row.col.f32.f16.f16.f32 "
                 "{%0,%1,%2,%3}, {%4,%5,%6,%7}, {%8,%9}, {%0,%1,%2,%3};"
                 : "+f"(c[0]), "+f"(c[1]), "+f"(c[2]), "+f"(c[3])
                 : "r"(a[0]), "r"(a[1]), "r"(a[2]), "r"(a[3]), "r"(b[0]), "r"(b[1]));
}
__device__ __forceinline__ void cp16(uint32_t dst, const void* src) {
    asm volatile("cp.async.cg.shared.global [%0], [%1], 16;" :: "r"(dst), "l"(src));
}

// ---------------------------------------------------------------------------
// Scratch (device globals; no allocation allowed)
// ---------------------------------------------------------------------------
__device__ float g_q[SEQ * DMODEL];
__device__ float g_k[SEQ * NKVH * HDIM];
__device__ float g_v[SEQ * NKVH * HDIM];

__device__ __half g_qh[SEQ * DMODEL], g_ql[SEQ * DMODEL];     // scaled, rope'd Q split
__device__ __half g_kh[SEQ * NKVH * HDIM], g_kl[SEQ * NKVH * HDIM];
__device__ __half g_vh[SEQ * NKVH * HDIM];

__device__ __nv_bfloat16 a_hi[SEQ * DMODEL], a_lo[SEQ * DMODEL];       // x split
__device__ __nv_bfloat16 att_hi[SEQ * DMODEL], att_lo[SEQ * DMODEL];   // attention out split
__device__ __nv_bfloat16 wqT_h[DMODEL * DMODEL], wqT_l[DMODEL * DMODEL];
__device__ __nv_bfloat16 wkT_h[1024 * DMODEL],  wkT_l[1024 * DMODEL];
__device__ __nv_bfloat16 wvT_h[1024 * DMODEL],  wvT_l[1024 * DMODEL];
__device__ __nv_bfloat16 woT_h[DMODEL * DMODEL], woT_l[DMODEL * DMODEL];

// ---------------------------------------------------------------------------
// Elementwise fp32 -> bf16 hi/lo split of x
// ---------------------------------------------------------------------------
__global__ void convert_x(const float* __restrict__ x)
{
    int i = blockIdx.x * blockDim.x + threadIdx.x;   // < 2M
    float4 v = *(const float4*)&x[(size_t)i * 4];
    float f[4] = {v.x, v.y, v.z, v.w};
#pragma unroll
    for (int j = 0; j < 4; j++) {
        __nv_bfloat16 h = __float2bfloat16(f[j]);
        __nv_bfloat16 l = __float2bfloat16(f[j] - __bfloat162float(h));
        a_hi[(size_t)i * 4 + j] = h;
        a_lo[(size_t)i * 4 + j] = l;
    }
}

// ---------------------------------------------------------------------------
// Transpose+split a weight:  w[K=4096, N] fp32  ->  wT[N, 4096] bf16 hi/lo
// ---------------------------------------------------------------------------
__global__ void transpose_w(const float* __restrict__ w,
                            __nv_bfloat16* __restrict__ oh,
                            __nv_bfloat16* __restrict__ ol, int N)
{
    __shared__ float t[32][33];
    const int tx = threadIdx.x, ty = threadIdx.y;
    const int n0 = blockIdx.x * 32, k0 = blockIdx.y * 32;
#pragma unroll
    for (int i = 0; i < 4; i++)
        t[ty + 8 * i][tx] = w[(size_t)(k0 + ty + 8 * i) * N + n0 + tx];
    __syncthreads();
#pragma unroll
    for (int i = 0; i < 4; i++) {
        float v = t[tx][ty + 8 * i];
        __nv_bfloat16 h = __float2bfloat16(v);
        __nv_bfloat16 l = __float2bfloat16(v - __bfloat162float(h));
        size_t off = (size_t)(n0 + ty + 8 * i) * DMODEL + k0 + tx;
        oh[off] = h;
        ol[off] = l;
    }
}

// ---------------------------------------------------------------------------
// bf16-split HMMA GEMM (unchanged, validated in R11)
// ---------------------------------------------------------------------------
#define OP_BYTES  (128 * 80)
#define STAGE_BYTES (4 * OP_BYTES)
#define GH_SMEM   (2 * STAGE_BYTES)

__global__ __launch_bounds__(256)
void gemm_hmma(const __nv_bfloat16* __restrict__ Ah, const __nv_bfloat16* __restrict__ Al,
               const __nv_bfloat16* __restrict__ BhT, const __nv_bfloat16* __restrict__ BlT,
               float* __restrict__ C, int N)
{
    extern __shared__ char smem_raw[];
    const uint32_t sb = smem_u32(smem_raw);
    const int tid  = threadIdx.x;
    const int wid  = tid >> 5;
    const int lane = tid & 31;
    const int wr   = wid & 3;
    const int wc   = wid >> 2;
    const int m0 = blockIdx.y * 128, n0 = blockIdx.x * 128;

    const __nv_bfloat16* gAh = Ah  + (size_t)m0 * DMODEL;
    const __nv_bfloat16* gAl = Al  + (size_t)m0 * DMODEL;
    const __nv_bfloat16* gBh = BhT + (size_t)n0 * DMODEL;
    const __nv_bfloat16* gBl = BlT + (size_t)n0 * DMODEL;

    auto stage = [&](int c, int s) {
        const uint32_t base = sb + s * STAGE_BYTES;
        const int koff = c * 32;
#pragma unroll
        for (int t = 0; t < 2; t++) {
            int seg = tid + t * 256;
            int row = seg >> 2, c16 = seg & 3;
            uint32_t so = row * 80 + c16 * 16;
            size_t   go = (size_t)row * DMODEL + koff + c16 * 8;
            cp16(base + so,                gAh + go);
            cp16(base + OP_BYTES + so,     gAl + go);
            cp16(base + 2 * OP_BYTES + so, gBh + go);
            cp16(base + 3 * OP_BYTES + so, gBl + go);
        }
        asm volatile("cp.async.commit_group;");
    };

    float acc[2][8][4];
#pragma unroll
    for (int i = 0; i < 2; i++)
#pragma unroll
        for (int j = 0; j < 8; j++)
#pragma unroll
            for (int q = 0; q < 4; q++) acc[i][j][q] = 0.f;

    const int mb = wr * 32;
    const uint32_t a_off = (mb + (lane & 15)) * 80 + ((lane >> 4) << 3) * 2;
    const uint32_t b_off = ((wc * 64) + (lane & 7) + ((lane >> 4) << 3)) * 80
                         + (((lane >> 3) & 1) << 3) * 2;

    stage(0, 0);
    const int NCH = DMODEL / 32;
    for (int c = 0; c < NCH; c++) {
        const int s = c & 1;
        if (c + 1 < NCH) {
            stage(c + 1, s ^ 1);
            asm volatile("cp.async.wait_group 1;");
        } else {
            asm volatile("cp.async.wait_group 0;");
        }
        __syncthreads();

        const uint32_t tAh = sb + s * STAGE_BYTES;
        const uint32_t tAl = tAh + OP_BYTES;
        const uint32_t tBh = tAh + 2 * OP_BYTES;
        const uint32_t tBl = tAh + 3 * OP_BYTES;

#pragma unroll
        for (int ks = 0; ks < 2; ks++) {
            const uint32_t kb = ks * 32;
#pragma unroll
            for (int pass = 0; pass < 3; pass++) {
                const uint32_t ta = (pass == 2) ? tAl : tAh;
                const uint32_t tb = (pass == 1) ? tBl : tBh;
                uint32_t a[2][4], b[4][4];
                ldsm_x4(a[0], ta + a_off + kb);
                ldsm_x4(a[1], ta + a_off + kb + 16 * 80);
#pragma unroll
                for (int q = 0; q < 4; q++)
                    ldsm_x4(b[q], tb + b_off + kb + q * 16 * 80);
#pragma unroll
                for (int i = 0; i < 2; i++)
#pragma unroll
                    for (int q = 0; q < 4; q++) {
                        mma16816(acc[i][2 * q],     a[i], &b[q][0]);
                        mma16816(acc[i][2 * q + 1], a[i], &b[q][2]);
                    }
            }
        }
        __syncthreads();
    }

    const int rbase = m0 + wr * 32 + (lane >> 2);
    const int cbase = n0 + wc * 64 + 2 * (lane & 3);
#pragma unroll
    for (int i = 0; i < 2; i++)
#pragma unroll
        for (int j = 0; j < 8; j++) {
            int r = rbase + i * 16;
            int cc = cbase + j * 8;
            *(float2*)&C[(size_t)r * N + cc]       = make_float2(acc[i][j][0], acc[i][j][1]);
            *(float2*)&C[(size_t)(r + 8) * N + cc] = make_float2(acc[i][j][2], acc[i][j][3]);
        }
}

// ---------------------------------------------------------------------------
// RoPE + fp16 conversion.  Q: rope, pre-scale by 1/sqrt(HD), split fp16 hi/lo.
// K: rope, split fp16 hi/lo.  V: convert fp16.
// ---------------------------------------------------------------------------
#define ATT_SCALE 0.08838834764831845f

__global__ void rope_conv(const float* __restrict__ cosb, const float* __restrict__ sinb)
{
    const int NQ = SEQ * NHEAD * 64;
    const int NK = SEQ * NKVH * 64;
    const int NV = SEQ * NKVH * 64;
    int idx = blockIdx.x * blockDim.x + threadIdx.x;
    if (idx < NQ) {
        int s = idx / (NHEAD * 64);
        int r = idx % (NHEAD * 64);
        int h = r / 64, i = r % 64;
        float c = cosb[s * 64 + i], sn = sinb[s * 64 + i];
        size_t off = (size_t)s * DMODEL + h * HDIM + 2 * i;
        float te = g_q[off], to = g_q[off + 1];
        float e = (te * c - to * sn) * ATT_SCALE;
        float o = (to * c + te * sn) * ATT_SCALE;
        __half eh = __float2half_rn(e), oh = __float2half_rn(o);
        g_qh[off] = eh;  g_ql[off] = __float2half_rn(e - __half2float(eh));
        g_qh[off + 1] = oh; g_ql[off + 1] = __float2half_rn(o - __half2float(oh));
    } else if (idx < NQ + NK) {
        int j = idx - NQ;
        int s = j / (NKVH * 64);
        int r = j % (NKVH * 64);
        int h = r / 64, i = r % 64;
        float c = cosb[s * 64 + i], sn = sinb[s * 64 + i];
        size_t off = (size_t)s * (NKVH * HDIM) + h * HDIM + 2 * i;
        float te = g_k[off], to = g_k[off + 1];
        float e = te * c - to * sn;
        float o = to * c + te * sn;
        __half eh = __float2half_rn(e), oh = __float2half_rn(o);
        g_kh[off] = eh;  g_kl[off] = __float2half_rn(e - __half2float(eh));
        g_kh[off + 1] = oh; g_kl[off + 1] = __float2half_rn(o - __half2float(oh));
    } else if (idx < NQ + NK + NV) {
        int j = idx - NQ - NK;
        size_t off = (size_t)j * 2;
        g_vh[off]     = __float2half_rn(g_v[off]);
        g_vh[off + 1] = __float2half_rn(g_v[off + 1]);
    }
}

// ---------------------------------------------------------------------------
// HMMA flash attention.  Block = (head, 128-query tile); BK=64; 8 warps.
//   S = Q*K^T via fp16 3-pass split (Qh*Kh + Ql*Kh + Qh*Kl), fp32 acc.
//   Online softmax fp32 (2 threads/row).  O += P*V via fp16 2-pass split P.
//   Output: bf16 hi/lo split (feeds HMMA O-projection).
// ---------------------------------------------------------------------------
#define BQ 128
#define BK 64
#define QSTR 272      // 128 fp16 + 16B pad
#define SSTR 66       // floats
#define PSTR 144      // 64 fp16 + 16B pad
#define OFF_QH 0
#define OFF_QL (OFF_QH + BQ * QSTR)
#define OFF_KH (OFF_QL + BQ * QSTR)
#define OFF_KL (OFF_KH + BK * QSTR)
#define OFF_V  (OFF_KL + BK * QSTR)
#define OFF_S  (OFF_V  + BK * QSTR)
#define OFF_PH (OFF_S  + BQ * SSTR * 4)
#define OFF_PL (OFF_PH + BQ * PSTR)
#define OFF_MET (OFF_PL + BQ * PSTR)
#define FA_SMEM (OFF_MET + 1024)

__global__ __launch_bounds__(256)
void attn_flash()
{
    extern __shared__ char smem_raw[];
    const uint32_t sb = smem_u32(smem_raw);
    const int tid = threadIdx.x, lane = tid & 31, w = tid >> 5;
    const int qt = (int)gridDim.x - 1 - (int)blockIdx.x;   // big tiles first
    const int h = blockIdx.y, kvh = h & (NKVH - 1);
    const int q0 = qt * BQ;
    const int nkt = 2 * qt + 2;
    const int rowbase = w * 16;

    float* Sf      = (float*)(smem_raw + OFF_S);
    float* alpha_s = (float*)(smem_raw + OFF_MET);
    float* l_s     = alpha_s + 128;

    const uint32_t aoffQ = (rowbase + (lane & 15)) * QSTR + ((lane >> 4) << 4);
    const uint32_t boffK = ((lane & 7) + ((lane >> 4) << 3)) * QSTR + (((lane >> 3) & 1) << 4);
    const uint32_t aoffP = (rowbase + (lane & 15)) * PSTR + ((lane >> 4) << 4);
    const uint32_t boffV = ((lane & 7) + (((lane >> 3) & 1) << 3)) * QSTR + ((lane >> 4) << 4);

    // stage Q (both splits)
#pragma unroll
    for (int t = 0; t < 8; t++) {
        int seg = tid + t * 256;              // 0..2047
        int row = seg >> 4, sg = seg & 15;
        size_t g = (size_t)(q0 + row) * DMODEL + h * HDIM + sg * 8;
        cp16(sb + OFF_QH + row * QSTR + sg * 16, g_qh + g);
        cp16(sb + OFF_QL + row * QSTR + sg * 16, g_ql + g);
    }
    asm volatile("cp.async.commit_group;");

    float oacc[16][4];
#pragma unroll
    for (int nt = 0; nt < 16; nt++)
#pragma unroll
        for (int q = 0; q < 4; q++) oacc[nt][q] = 0.f;

    float m = -INFINITY, l = 0.f;
    const int srow = tid >> 1, shalf = tid & 1;
    const int gq = q0 + srow;

    for (int kt = 0; kt < nkt; kt++) {
        const int k0 = kt * BK;
        // stage K/V tile
#pragma unroll
        for (int t = 0; t < 4; t++) {
            int seg = tid + t * 256;          // 0..1023
            int row = seg >> 4, sg = seg & 15;
            size_t g = (size_t)(k0 + row) * (NKVH * HDIM) + kvh * HDIM + sg * 8;
            cp16(sb + OFF_KH + row * QSTR + sg * 16, g_kh + g);
            cp16(sb + OFF_KL + row * QSTR + sg * 16, g_kl + g);
            cp16(sb + OFF_V  + row * QSTR + sg * 16, g_vh + g);
        }
        asm volatile("cp.async.commit_group;");
        asm volatile("cp.async.wait_group 0;");
        __syncthreads();

        // S = Q*K^T (3-pass fp16 split)
        float sacc[8][4];
#pragma unroll
        for (int nt = 0; nt < 8; nt++)
#pragma unroll
            for (int q = 0; q < 4; q++) sacc[nt][q] = 0.f;

#pragma unroll
        for (int pass = 0; pass < 3; pass++) {
            const uint32_t qb = sb + (pass == 1 ? OFF_QL : OFF_QH) + aoffQ;
            const uint32_t kb = sb + (pass == 2 ? OFF_KL : OFF_KH) + boffK;
#pragma unroll
            for (int ks = 0; ks < 8; ks++) {
                uint32_t a[4];
                ldsm_x4(a, qb + ks * 32);
#pragma unroll
                for (int g2 = 0; g2 < 4; g2++) {
                    uint32_t b[4];
                    ldsm_x4(b, kb + g2 * 16 * QSTR + ks * 32);
                    mma16816h(sacc[2 * g2],     a, &b[0]);
                    mma16816h(sacc[2 * g2 + 1], a, &b[2]);
                }
            }
        }
        // fragments -> S smem
        {
            int r = rowbase + (lane >> 2), c = 2 * (lane & 3);
#pragma unroll
            for (int nt = 0; nt < 8; nt++) {
                *(float2*)&Sf[r * SSTR + nt * 8 + c]       = make_float2(sacc[nt][0], sacc[nt][1]);
                *(float2*)&Sf[(r + 8) * SSTR + nt * 8 + c] = make_float2(sacc[nt][2], sacc[nt][3]);
            }
        }
        __syncthreads();

        // online softmax (2 threads per row)
        {
            const int cb = shalf * 32;
            float mx = -1e30f;
#pragma unroll
            for (int j = 0; j < 32; j++) {
                int gk = k0 + cb + j;
                float s = Sf[srow * SSTR + cb + j];
                mx = fmaxf(mx, gk <= gq ? s : -1e30f);
            }
            mx = fmaxf(mx, __shfl_xor_sync(0xffffffffu, mx, 1));
            float mn = fmaxf(m, mx);
            float al = __expf(m - mn);
            float ls = 0.f;
            __half* Ph = (__half*)(smem_raw + OFF_PH + srow * PSTR);
            __half* Pl = (__half*)(smem_raw + OFF_PL + srow * PSTR);
#pragma unroll
            for (int j = 0; j < 32; j++) {
                int gk = k0 + cb + j;
                float s = Sf[srow * SSTR + cb + j];
                float p = (gk <= gq) ? __expf(s - mn) : 0.f;
                ls += p;
                __half ph = __float2half_rn(p);
                Ph[cb + j] = ph;
                Pl[cb + j] = __float2half_rn(p - __half2float(ph));
            }
            ls += __shfl_xor_sync(0xffffffffu, ls, 1);
            l = l * al + ls;
            m = mn;
            if (!shalf) { alpha_s[srow] = al; l_s[srow] = l; }
        }
        __syncthreads();

        // rescale O; O += P*V (2-pass split P)
        {
            float a0 = alpha_s[rowbase + (lane >> 2)];
            float a1 = alpha_s[rowbase + (lane >> 2) + 8];
#pragma unroll
            for (int nt = 0; nt < 16; nt++) {
                oacc[nt][0] *= a0; oacc[nt][1] *= a0;
                oacc[nt][2] *= a1; oacc[nt][3] *= a1;
            }
#pragma unroll
            for (int ks = 0; ks < 4; ks++) {
                uint32_t vfr[8][4];
#pragma unroll
                for (int g2 = 0; g2 < 8; g2++)
                    ldsm_x4_t(vfr[g2], sb + OFF_V + boffV + ks * 16 * QSTR + g2 * 32);
#pragma unroll
                for (int pass = 0; pass < 2; pass++) {
                    uint32_t a[4];
                    ldsm_x4(a, sb + (pass ? OFF_PL : OFF_PH) + aoffP + ks * 32);
#pragma unroll
                    for (int g2 = 0; g2 < 8; g2++) {
                        mma16816h(oacc[2 * g2],     a, &vfr[g2][0]);
                        mma16816h(oacc[2 * g2 + 1], a, &vfr[g2][2]);
                    }
                }
            }
        }
        __syncthreads();
    }

    // epilogue: normalize, bf16 hi/lo split, store
    {
        const int r0 = rowbase + (lane >> 2);
        const float inv0 = 1.f / l_s[r0];
        const float inv1 = 1.f / l_s[r0 + 8];
        const int s0 = q0 + r0, s1 = s0 + 8;
#pragma unroll
        for (int nt = 0; nt < 16; nt++) {
            int c = nt * 8 + 2 * (lane & 3);
            size_t i0 = (size_t)s0 * DMODEL + h * HDIM + c;
            size_t i1 = (size_t)s1 * DMODEL + h * HDIM + c;
            float v0 = oacc[nt][0] * inv0, v1 = oacc[nt][1] * inv0;
            float v2 = oacc[nt][2] * inv1, v3 = oacc[nt][3] * inv1;
            __nv_bfloat16 h0 = __float2bfloat16(v0), h1 = __float2bfloat16(v1);
            __nv_bfloat16 h2 = __float2bfloat16(v2), h3 = __float2bfloat16(v3);
            *(__nv_bfloat162*)&att_hi[i0] = __halves2bfloat162(h0, h1);
            *(__nv_bfloat162*)&att_hi[i1] = __halves2bfloat162(h2, h3);
            *(__nv_bfloat162*)&att_lo[i0] = __halves2bfloat162(
                __float2bfloat16(v0 - __bfloat162float(h0)),
                __float2bfloat16(v1 - __bfloat162float(h1)));
            *(__nv_bfloat162*)&att_lo[i1] = __halves2bfloat162(
                __float2bfloat16(v2 - __bfloat162float(h2)),
                __float2bfloat16(v3 - __bfloat162float(h3)));
        }
    }
}

// ---------------------------------------------------------------------------
// Launch
// ---------------------------------------------------------------------------
extern "C" void kernel_launch(void* const* d_in, const int* in_sizes, int n_in,
                              void* d_out, int out_size)
{
    const float* x    = (const float*)d_in[0];
    const float* wq   = (const float*)d_in[1];
    const float* wk   = (const float*)d_in[2];
    const float* wv   = (const float*)d_in[3];
    const float* wo   = (const float*)d_in[4];
    const float* fcos = (const float*)d_in[5];
    const float* fsin = (const float*)d_in[6];
    float* out = (float*)d_out;

    float *gq, *gk, *gv;
    cudaGetSymbolAddress((void**)&gq, g_q);
    cudaGetSymbolAddress((void**)&gk, g_k);
    cudaGetSymbolAddress((void**)&gv, g_v);
    __nv_bfloat16 *pah, *pal, *path, *patl;
    __nv_bfloat16 *pwqh, *pwql, *pwkh, *pwkl, *pwvh, *pwvl, *pwoh, *pwol;
    cudaGetSymbolAddress((void**)&pah, a_hi);
    cudaGetSymbolAddress((void**)&pal, a_lo);
    cudaGetSymbolAddress((void**)&path, att_hi);
    cudaGetSymbolAddress((void**)&patl, att_lo);
    cudaGetSymbolAddress((void**)&pwqh, wqT_h);
    cudaGetSymbolAddress((void**)&pwql, wqT_l);
    cudaGetSymbolAddress((void**)&pwkh, wkT_h);
    cudaGetSymbolAddress((void**)&pwkl, wkT_l);
    cudaGetSymbolAddress((void**)&pwvh, wvT_h);
    cudaGetSymbolAddress((void**)&pwvl, wvT_l);
    cudaGetSymbolAddress((void**)&pwoh, woT_h);
    cudaGetSymbolAddress((void**)&pwol, woT_l);

    cudaFuncSetAttribute(gemm_hmma, cudaFuncAttributeMaxDynamicSharedMemorySize, GH_SMEM);
    cudaFuncSetAttribute(attn_flash, cudaFuncAttributeMaxDynamicSharedMemorySize, FA_SMEM);

    // Split x; transpose+split weights
    convert_x<<<(SEQ * DMODEL / 4) / 256, 256>>>(x);
    transpose_w<<<dim3(DMODEL / 32, DMODEL / 32), dim3(32, 8)>>>(wq, pwqh, pwql, DMODEL);
    transpose_w<<<dim3(1024 / 32, DMODEL / 32), dim3(32, 8)>>>(wk, pwkh, pwkl, 1024);
    transpose_w<<<dim3(1024 / 32, DMODEL / 32), dim3(32, 8)>>>(wv, pwvh, pwvl, 1024);
    transpose_w<<<dim3(DMODEL / 32, DMODEL / 32), dim3(32, 8)>>>(wo, pwoh, pwol, DMODEL);

    // QKV projections (HMMA)
    gemm_hmma<<<dim3(DMODEL / 128, SEQ / 128), 256, GH_SMEM>>>(pah, pal, pwqh, pwql, gq, DMODEL);
    gemm_hmma<<<dim3(1024 / 128, SEQ / 128), 256, GH_SMEM>>>(pah, pal, pwkh, pwkl, gk, 1024);
    gemm_hmma<<<dim3(1024 / 128, SEQ / 128), 256, GH_SMEM>>>(pah, pal, pwvh, pwvl, gv, 1024);

    // RoPE + fp16 conversions
    {
        int np = SEQ * (NHEAD + NKVH + NKVH) * 64;
        rope_conv<<<(np + 255) / 256, 256>>>(fcos, fsin);
    }

    // Flash attention (HMMA)
    attn_flash<<<dim3(SEQ / BQ, NHEAD), 256, FA_SMEM>>>();

    // Output projection (HMMA) -> d_out
    gemm_hmma<<<dim3(DMODEL / 128, SEQ / 128), 256, GH_SMEM>>>(path, patl, pwoh, pwol, out, DMODEL);
}

// round 15
// speedup vs baseline: 3.7773x; 1.0329x over previous
#include <cuda_runtime.h>
#include <cuda_bf16.h>
#include <cuda_fp16.h>
#include <math.h>
#include <stdint.h>

// Problem constants
#define SEQ    2048
#define DMODEL 4096
#define NHEAD  32
#define NKVH   8
#define HDIM   128

// ---------------------------------------------------------------------------
// Helpers
// ---------------------------------------------------------------------------
__device__ __forceinline__ uint32_t smem_u32(const void* p) {
    uint32_t a;
    asm("{ .reg .u64 t; cvta.to.shared.u64 t, %1; cvt.u32.u64 %0, t; }" : "=r"(a) : "l"(p));
    return a;
}
__device__ __forceinline__ void ldsm_x4(uint32_t* r, uint32_t addr) {
    asm volatile("ldmatrix.sync.aligned.m8n8.x4.shared.b16 {%0,%1,%2,%3}, [%4];"
                 : "=r"(r[0]), "=r"(r[1]), "=r"(r[2]), "=r"(r[3]) : "r"(addr));
}
__device__ __forceinline__ void ldsm_x4_t(uint32_t* r, uint32_t addr) {
    asm volatile("ldmatrix.sync.aligned.m8n8.x4.trans.shared.b16 {%0,%1,%2,%3}, [%4];"
                 : "=r"(r[0]), "=r"(r[1]), "=r"(r[2]), "=r"(r[3]) : "r"(addr));
}
__device__ __forceinline__ void mma16816(float* c, const uint32_t* a, const uint32_t* b) {
    asm volatile("mma.sync.aligned.m16n8k16.row.col.f32.bf16.bf16.f32 "
                 "{%0,%1,%2,%3}, {%4,%5,%6,%7}, {%8,%9}, {%0,%1,%2,%3};"
                 : "+f"(c[0]), "+f"(c[1]), "+f"(c[2]), "+f"(c[3])
                 : "r"(a[0]), "r"(a[1]), "r"(a[2]), "r"(a[3]), "r"(b[0]), "r"(b[1]));
}
__device__ __forceinline__ void mma16816h(float* c, const uint32_t* a, const uint32_t* b) {
    asm volatile("mma.sync.aligned.m16n8k16.row.col.f32.f16.f16.f32 "
                 "{%0,%1,%2,%3}, {%4,%5,%6,%7}, {%8,%9}, {%0,%1,%2,%3};"
                 : "+f"(c[0]), "+f"(c[1]), "+f"(c[2]), "+f"(c[3])
                 : "r"(a[0]), "r"(a[1]), "r"(a[2]), "r"(a[3]), "r"(b[0]), "r"(b[1]));
}
__device__ __forceinline__ void cp16(uint32_t dst, const void* src) {
    asm volatile("cp.async.cg.shared.global [%0], [%1], 16;" :: "r"(dst), "l"(src));
}
__device__ __forceinline__ uint32_t packh2(__half a, __half b) {
    __half2 h = __halves2half2(a, b);
    return *(uint32_t*)&h;
}

// ---------------------------------------------------------------------------
// Scratch (device globals; no allocation allowed)
// ---------------------------------------------------------------------------
__device__ float g_q[SEQ * DMODEL];
__device__ float g_k[SEQ * NKVH * HDIM];
__device__ float g_v[SEQ * NKVH * HDIM];

__device__ __half g_qh[SEQ * DMODEL], g_ql[SEQ * DMODEL];     // scaled, rope'd Q split
__device__ __half g_kh[SEQ * NKVH * HDIM], g_kl[SEQ * NKVH * HDIM];
__device__ __half g_vh[SEQ * NKVH * HDIM];

__device__ __nv_bfloat16 a_hi[SEQ * DMODEL], a_lo[SEQ * DMODEL];       // x split
__device__ __nv_bfloat16 att_hi[SEQ * DMODEL], att_lo[SEQ * DMODEL];   // attention out split
__device__ __nv_bfloat16 wqT_h[DMODEL * DMODEL], wqT_l[DMODEL * DMODEL];
__device__ __nv_bfloat16 wkT_h[1024 * DMODEL],  wkT_l[1024 * DMODEL];
__device__ __nv_bfloat16 wvT_h[1024 * DMODEL],  wvT_l[1024 * DMODEL];
__device__ __nv_bfloat16 woT_h[DMODEL * DMODEL], woT_l[DMODEL * DMODEL];

// ---------------------------------------------------------------------------
// Elementwise fp32 -> bf16 hi/lo split of x
// ---------------------------------------------------------------------------
__global__ void convert_x(const float* __restrict__ x)
{
    int i = blockIdx.x * blockDim.x + threadIdx.x;   // < 2M
    float4 v = *(const float4*)&x[(size_t)i * 4];
    float f[4] = {v.x, v.y, v.z, v.w};
#pragma unroll
    for (int j = 0; j < 4; j++) {
        __nv_bfloat16 h = __float2bfloat16(f[j]);
        __nv_bfloat16 l = __float2bfloat16(f[j] - __bfloat162float(h));
        a_hi[(size_t)i * 4 + j] = h;
        a_lo[(size_t)i * 4 + j] = l;
    }
}

// ---------------------------------------------------------------------------
// Transpose+split a weight:  w[K=4096, N] fp32  ->  wT[N, 4096] bf16 hi/lo
// ---------------------------------------------------------------------------
__global__ void transpose_w(const float* __restrict__ w,
                            __nv_bfloat16* __restrict__ oh,
                            __nv_bfloat16* __restrict__ ol, int N)
{
    __shared__ float t[32][33];
    const int tx = threadIdx.x, ty = threadIdx.y;
    const int n0 = blockIdx.x * 32, k0 = blockIdx.y * 32;
#pragma unroll
    for (int i = 0; i < 4; i++)
        t[ty + 8 * i][tx] = w[(size_t)(k0 + ty + 8 * i) * N + n0 + tx];
    __syncthreads();
#pragma unroll
    for (int i = 0; i < 4; i++) {
        float v = t[tx][ty + 8 * i];
        __nv_bfloat16 h = __float2bfloat16(v);
        __nv_bfloat16 l = __float2bfloat16(v - __bfloat162float(h));
        size_t off = (size_t)(n0 + ty + 8 * i) * DMODEL + k0 + tx;
        oh[off] = h;
        ol[off] = l;
    }
}

// ---------------------------------------------------------------------------
// bf16-split HMMA GEMM, 4-stage cp.async pipeline.
//   C[2048, N] = A[2048, 4096] @ B[4096, N]; split C = Ah*Bh + Ah*Bl + Al*Bh.
// ---------------------------------------------------------------------------
#define OP_BYTES    (128 * 80)
#define STAGE_BYTES (4 * OP_BYTES)        // 40960
#define NSTAGE      4
#define GH_SMEM     (NSTAGE * STAGE_BYTES)  // 163840

__global__ __launch_bounds__(256)
void gemm_hmma(const __nv_bfloat16* __restrict__ Ah, const __nv_bfloat16* __restrict__ Al,
               const __nv_bfloat16* __restrict__ BhT, const __nv_bfloat16* __restrict__ BlT,
               float* __restrict__ C, int N)
{
    extern __shared__ char smem_raw[];
    const uint32_t sb = smem_u32(smem_raw);
    const int tid  = threadIdx.x;
    const int wid  = tid >> 5;
    const int lane = tid & 31;
    const int wr   = wid & 3;
    const int wc   = wid >> 2;
    const int m0 = blockIdx.y * 128, n0 = blockIdx.x * 128;

    const __nv_bfloat16* gAh = Ah  + (size_t)m0 * DMODEL;
    const __nv_bfloat16* gAl = Al  + (size_t)m0 * DMODEL;
    const __nv_bfloat16* gBh = BhT + (size_t)n0 * DMODEL;
    const __nv_bfloat16* gBl = BlT + (size_t)n0 * DMODEL;

    auto stage = [&](int c, int s) {
        const uint32_t base = sb + s * STAGE_BYTES;
        const int koff = c * 32;
#pragma unroll
        for (int t = 0; t < 2; t++) {
            int seg = tid + t * 256;
            int row = seg >> 2, c16 = seg & 3;
            uint32_t so = row * 80 + c16 * 16;
            size_t   go = (size_t)row * DMODEL + koff + c16 * 8;
            cp16(base + so,                gAh + go);
            cp16(base + OP_BYTES + so,     gAl + go);
            cp16(base + 2 * OP_BYTES + so, gBh + go);
            cp16(base + 3 * OP_BYTES + so, gBl + go);
        }
        asm volatile("cp.async.commit_group;");
    };

    float acc[2][8][4];
#pragma unroll
    for (int i = 0; i < 2; i++)
#pragma unroll
        for (int j = 0; j < 8; j++)
#pragma unroll
            for (int q = 0; q < 4; q++) acc[i][j][q] = 0.f;

    const int mb = wr * 32;
    const uint32_t a_off = (mb + (lane & 15)) * 80 + ((lane >> 4) << 3) * 2;
    const uint32_t b_off = ((wc * 64) + (lane & 7) + ((lane >> 4) << 3)) * 80
                         + (((lane >> 3) & 1) << 3) * 2;

    stage(0, 0);
    stage(1, 1);
    stage(2, 2);
    const int NCH = DMODEL / 32;          // 128
    for (int c = 0; c < NCH; c++) {
        asm volatile("cp.async.wait_group 2;");   // group c retired
        __syncthreads();                          // all threads past wait; buf (c-1)&3 free
        if (c + 3 < NCH) stage(c + 3, (c + 3) & 3);

        const uint32_t tAh = sb + (c & 3) * STAGE_BYTES;
        const uint32_t tAl = tAh + OP_BYTES;
        const uint32_t tBh = tAh + 2 * OP_BYTES;
        const uint32_t tBl = tAh + 3 * OP_BYTES;

#pragma unroll
        for (int ks = 0; ks < 2; ks++) {
            const uint32_t kb = ks * 32;
#pragma unroll
            for (int pass = 0; pass < 3; pass++) {
                const uint32_t ta = (pass == 2) ? tAl : tAh;
                const uint32_t tb = (pass == 1) ? tBl : tBh;
                uint32_t a[2][4], b[4][4];
                ldsm_x4(a[0], ta + a_off + kb);
                ldsm_x4(a[1], ta + a_off + kb + 16 * 80);
#pragma unroll
                for (int q = 0; q < 4; q++)
                    ldsm_x4(b[q], tb + b_off + kb + q * 16 * 80);
#pragma unroll
                for (int i = 0; i < 2; i++)
#pragma unroll
                    for (int q = 0; q < 4; q++) {
                        mma16816(acc[i][2 * q],     a[i], &b[q][0]);
                        mma16816(acc[i][2 * q + 1], a[i], &b[q][2]);
                    }
            }
        }
    }

    const int rbase = m0 + wr * 32 + (lane >> 2);
    const int cbase = n0 + wc * 64 + 2 * (lane & 3);
#pragma unroll
    for (int i = 0; i < 2; i++)
#pragma unroll
        for (int j = 0; j < 8; j++) {
            int r = rbase + i * 16;
            int cc = cbase + j * 8;
            *(float2*)&C[(size_t)r * N + cc]       = make_float2(acc[i][j][0], acc[i][j][1]);
            *(float2*)&C[(size_t)(r + 8) * N + cc] = make_float2(acc[i][j][2], acc[i][j][3]);
        }
}

// ---------------------------------------------------------------------------
// RoPE + fp16 conversion.  Q: rope, pre-scale by 1/sqrt(HD), split fp16 hi/lo.
// K: rope, split fp16 hi/lo.  V: convert fp16.
// ---------------------------------------------------------------------------
#define ATT_SCALE 0.08838834764831845f

__global__ void rope_conv(const float* __restrict__ cosb, const float* __restrict__ sinb)
{
    const int NQ = SEQ * NHEAD * 64;
    const int NK = SEQ * NKVH * 64;
    const int NV = SEQ * NKVH * 64;
    int idx = blockIdx.x * blockDim.x + threadIdx.x;
    if (idx < NQ) {
        int s = idx / (NHEAD * 64);
        int r = idx % (NHEAD * 64);
        int h = r / 64, i = r % 64;
        float c = cosb[s * 64 + i], sn = sinb[s * 64 + i];
        size_t off = (size_t)s * DMODEL + h * HDIM + 2 * i;
        float te = g_q[off], to = g_q[off + 1];
        float e = (te * c - to * sn) * ATT_SCALE;
        float o = (to * c + te * sn) * ATT_SCALE;
        __half eh = __float2half_rn(e), oh = __float2half_rn(o);
        g_qh[off] = eh;  g_ql[off] = __float2half_rn(e - __half2float(eh));
        g_qh[off + 1] = oh; g_ql[off + 1] = __float2half_rn(o - __half2float(oh));
    } else if (idx < NQ + NK) {
        int j = idx - NQ;
        int s = j / (NKVH * 64);
        int r = j % (NKVH * 64);
        int h = r / 64, i = r % 64;
        float c = cosb[s * 64 + i], sn = sinb[s * 64 + i];
        size_t off = (size_t)s * (NKVH * HDIM) + h * HDIM + 2 * i;
        float te = g_k[off], to = g_k[off + 1];
        float e = te * c - to * sn;
        float o = to * c + te * sn;
        __half eh = __float2half_rn(e), oh = __float2half_rn(o);
        g_kh[off] = eh;  g_kl[off] = __float2half_rn(e - __half2float(eh));
        g_kh[off + 1] = oh; g_kl[off + 1] = __float2half_rn(o - __half2float(oh));
    } else if (idx < NQ + NK + NV) {
        int j = idx - NQ - NK;
        size_t off = (size_t)j * 2;
        g_vh[off]     = __float2half_rn(g_v[off]);
        g_vh[off + 1] = __float2half_rn(g_v[off + 1]);
    }
}

// ---------------------------------------------------------------------------
// HMMA flash attention, FA2-style register softmax.
//   Block = (head, 128-query tile); BK=64; 8 warps; K/V double-buffered.
//   S fragments -> mask/max/exp/sum in registers (shfl over 4-lane groups),
//   P hi/lo fp16 fragments packed in-register (S layout == P A-fragment layout).
// ---------------------------------------------------------------------------
#define BQ 128
#define BK 64
#define KSTR 272                       // bytes per row (128 fp16 + 16B pad)
#define AOFF_QH 0
#define AOFF_QL (BQ * KSTR)            // 34816
#define AOFF_ST (2 * BQ * KSTR)        // 69632
#define KV_STG  (3 * BK * KSTR)        // 52224 per stage: KH | KL | V
#define FA_SMEM (AOFF_ST + 2 * KV_STG) // 174080

__global__ __launch_bounds__(256)
void attn_flash()
{
    extern __shared__ char smem_raw[];
    const uint32_t sb = smem_u32(smem_raw);
    const int tid = threadIdx.x, lane = tid & 31, w = tid >> 5;
    const int qt = (int)gridDim.x - 1 - (int)blockIdx.x;   // big tiles first
    const int h = blockIdx.y, kvh = h & (NKVH - 1);
    const int q0 = qt * BQ;
    const int nkt = 2 * qt + 2;
    const int rowbase = w * 16;

    const uint32_t aoffQ = (rowbase + (lane & 15)) * KSTR + ((lane >> 4) << 4);
    const uint32_t boffK = ((lane & 7) + ((lane >> 4) << 3)) * KSTR + (((lane >> 3) & 1) << 4);
    const uint32_t boffV = ((lane & 7) + (((lane >> 3) & 1) << 3)) * KSTR + ((lane >> 4) << 4);

    // stage Q (both splits) — group 0
#pragma unroll
    for (int t = 0; t < 8; t++) {
        int seg = tid + t * 256;
        int row = seg >> 4, sg = seg & 15;
        size_t g = (size_t)(q0 + row) * DMODEL + h * HDIM + sg * 8;
        cp16(sb + AOFF_QH + row * KSTR + sg * 16, g_qh + g);
        cp16(sb + AOFF_QL + row * KSTR + sg * 16, g_ql + g);
    }
    asm volatile("cp.async.commit_group;");

    auto stage_kv = [&](int kt, int s) {
        const uint32_t base = sb + AOFF_ST + s * KV_STG;
        const int k0 = kt * BK;
#pragma unroll
        for (int t = 0; t < 4; t++) {
            int seg = tid + t * 256;
            int row = seg >> 4, sg = seg & 15;
            size_t g = (size_t)(k0 + row) * (NKVH * HDIM) + kvh * HDIM + sg * 8;
            cp16(base + row * KSTR + sg * 16,                 g_kh + g);
            cp16(base + BK * KSTR + row * KSTR + sg * 16,     g_kl + g);
            cp16(base + 2 * BK * KSTR + row * KSTR + sg * 16, g_vh + g);
        }
        asm volatile("cp.async.commit_group;");
    };

    stage_kv(0, 0);   // group 1

    float oacc[16][4];
#pragma unroll
    for (int nt = 0; nt < 16; nt++)
#pragma unroll
        for (int q = 0; q < 4; q++) oacc[nt][q] = 0.f;

    float m0 = -INFINITY, m1 = -INFINITY, l0 = 0.f, l1 = 0.f;
    const int gq0 = q0 + rowbase + (lane >> 2);
    const int gq1 = gq0 + 8;

    for (int kt = 0; kt < nkt; kt++) {
        const int k0 = kt * BK;
        const int s = kt & 1;
        asm volatile("cp.async.wait_group 0;");
        __syncthreads();
        if (kt + 1 < nkt) stage_kv(kt + 1, s ^ 1);

        const bool active = (k0 <= q0 + rowbase + 15);
        if (active) {
            const uint32_t kvb = sb + AOFF_ST + s * KV_STG;

            // S = Q*K^T (3-pass fp16 split), fragments in registers
            float sacc[8][4];
#pragma unroll
            for (int nt = 0; nt < 8; nt++)
#pragma unroll
                for (int q = 0; q < 4; q++) sacc[nt][q] = 0.f;

#pragma unroll
            for (int pass = 0; pass < 3; pass++) {
                const uint32_t qb = sb + (pass == 1 ? AOFF_QL : AOFF_QH) + aoffQ;
                const uint32_t kb = kvb + (pass == 2 ? BK * KSTR : 0) + boffK;
#pragma unroll
                for (int ks = 0; ks < 8; ks++) {
                    uint32_t a[4];
                    ldsm_x4(a, qb + ks * 32);
#pragma unroll
                    for (int g2 = 0; g2 < 4; g2++) {
                        uint32_t b[4];
                        ldsm_x4(b, kb + g2 * 16 * KSTR + ks * 32);
                        mma16816h(sacc[2 * g2],     a, &b[0]);
                        mma16816h(sacc[2 * g2 + 1], a, &b[2]);
                    }
                }
            }

            // mask + register softmax
            const int colb = k0 + 2 * (lane & 3);
            float mx0 = -1e30f, mx1 = -1e30f;
#pragma unroll
            for (int nt = 0; nt < 8; nt++) {
                int c0 = colb + 8 * nt, c1 = c0 + 1;
                if (c0 > gq0) sacc[nt][0] = -1e30f;
                if (c1 > gq0) sacc[nt][1] = -1e30f;
                if (c0 > gq1) sacc[nt][2] = -1e30f;
                if (c1 > gq1) sacc[nt][3] = -1e30f;
                mx0 = fmaxf(mx0, fmaxf(sacc[nt][0], sacc[nt][1]));
                mx1 = fmaxf(mx1, fmaxf(sacc[nt][2], sacc[nt][3]));
            }
            mx0 = fmaxf(mx0, __shfl_xor_sync(0xffffffffu, mx0, 1));
            mx0 = fmaxf(mx0, __shfl_xor_sync(0xffffffffu, mx0, 2));
            mx1 = fmaxf(mx1, __shfl_xor_sync(0xffffffffu, mx1, 1));
            mx1 = fmaxf(mx1, __shfl_xor_sync(0xffffffffu, mx1, 2));
            float mn0 = fmaxf(m0, mx0), mn1 = fmaxf(m1, mx1);
            float al0 = __expf(m0 - mn0), al1 = __expf(m1 - mn1);
            m0 = mn0; m1 = mn1;

            uint32_t ph[4][4], pl[4][4];
            float ls0 = 0.f, ls1 = 0.f;
#pragma unroll
            for (int nt = 0; nt < 8; nt++) {
                float p0 = __expf(sacc[nt][0] - mn0);
                float p1 = __expf(sacc[nt][1] - mn0);
                float p2 = __expf(sacc[nt][2] - mn1);
                float p3 = __expf(sacc[nt][3] - mn1);
                ls0 += p0 + p1; ls1 += p2 + p3;
                __half h0 = __float2half_rn(p0), h1 = __float2half_rn(p1);
                __half h2 = __float2half_rn(p2), h3 = __float2half_rn(p3);
                int ks = nt >> 1, half = (nt & 1) << 1;
                ph[ks][half]     = packh2(h0, h1);
                ph[ks][half + 1] = packh2(h2, h3);
                pl[ks][half]     = packh2(__float2half_rn(p0 - __half2float(h0)),
                                          __float2half_rn(p1 - __half2float(h1)));
                pl[ks][half + 1] = packh2(__float2half_rn(p2 - __half2float(h2)),
                                          __float2half_rn(p3 - __half2float(h3)));
            }
            ls0 += __shfl_xor_sync(0xffffffffu, ls0, 1);
            ls0 += __shfl_xor_sync(0xffffffffu, ls0, 2);
            ls1 += __shfl_xor_sync(0xffffffffu, ls1, 1);
            ls1 += __shfl_xor_sync(0xffffffffu, ls1, 2);
            l0 = l0 * al0 + ls0;
            l1 = l1 * al1 + ls1;

#pragma unroll
            for (int nt = 0; nt < 16; nt++) {
                oacc[nt][0] *= al0; oacc[nt][1] *= al0;
                oacc[nt][2] *= al1; oacc[nt][3] *= al1;
            }

            // O += P*V (2-pass split P), V via ldmatrix.trans
            const uint32_t vb = kvb + 2 * BK * KSTR + boffV;
#pragma unroll
            for (int ks = 0; ks < 4; ks++) {
                uint32_t vfr[8][4];
#pragma unroll
                for (int g2 = 0; g2 < 8; g2++)
                    ldsm_x4_t(vfr[g2], vb + ks * 16 * KSTR + g2 * 32);
#pragma unroll
                for (int g2 = 0; g2 < 8; g2++) {
                    mma16816h(oacc[2 * g2],     ph[ks], &vfr[g2][0]);
                    mma16816h(oacc[2 * g2 + 1], ph[ks], &vfr[g2][2]);
                }
#pragma unroll
                for (int g2 = 0; g2 < 8; g2++) {
                    mma16816h(oacc[2 * g2],     pl[ks], &vfr[g2][0]);
                    mma16816h(oacc[2 * g2 + 1], pl[ks], &vfr[g2][2]);
                }
            }
        }
        __syncthreads();   // all warps done with stage s before it is overwritten
    }

    // epilogue: normalize, bf16 hi/lo split, store
    {
        const float inv0 = 1.f / l0;
        const float inv1 = 1.f / l1;
        const int s0 = gq0, s1 = gq1;
#pragma unroll
        for (int nt = 0; nt < 16; nt++) {
            int c = nt * 8 + 2 * (lane & 3);
            size_t i0 = (size_t)s0 * DMODEL + h * HDIM + c;
            size_t i1 = (size_t)s1 * DMODEL + h * HDIM + c;
            float v0 = oacc[nt][0] * inv0, v1 = oacc[nt][1] * inv0;
            float v2 = oacc[nt][2] * inv1, v3 = oacc[nt][3] * inv1;
            __nv_bfloat16 h0 = __float2bfloat16(v0), h1 = __float2bfloat16(v1);
            __nv_bfloat16 h2 = __float2bfloat16(v2), h3 = __float2bfloat16(v3);
            *(__nv_bfloat162*)&att_hi[i0] = __halves2bfloat162(h0, h1);
            *(__nv_bfloat162*)&att_hi[i1] = __halves2bfloat162(h2, h3);
            *(__nv_bfloat162*)&att_lo[i0] = __halves2bfloat162(
                __float2bfloat16(v0 - __bfloat162float(h0)),
                __float2bfloat16(v1 - __bfloat162float(h1)));
            *(__nv_bfloat162*)&att_lo[i1] = __halves2bfloat162(
                __float2bfloat16(v2 - __bfloat162float(h2)),
                __float2bfloat16(v3 - __bfloat162float(h3)));
        }
    }
}

// ---------------------------------------------------------------------------
// Launch
// ---------------------------------------------------------------------------
extern "C" void kernel_launch(void* const* d_in, const int* in_sizes, int n_in,
                              void* d_out, int out_size)
{
    const float* x    = (const float*)d_in[0];
    const float* wq   = (const float*)d_in[1];
    const float* wk   = (const float*)d_in[2];
    const float* wv   = (const float*)d_in[3];
    const float* wo   = (const float*)d_in[4];
    const float* fcos = (const float*)d_in[5];
    const float* fsin = (const float*)d_in[6];
    float* out = (float*)d_out;

    float *gq, *gk, *gv;
    cudaGetSymbolAddress((void**)&gq, g_q);
    cudaGetSymbolAddress((void**)&gk, g_k);
    cudaGetSymbolAddress((void**)&gv, g_v);
    __nv_bfloat16 *pah, *pal, *path, *patl;
    __nv_bfloat16 *pwqh, *pwql, *pwkh, *pwkl, *pwvh, *pwvl, *pwoh, *pwol;
    cudaGetSymbolAddress((void**)&pah, a_hi);
    cudaGetSymbolAddress((void**)&pal, a_lo);
    cudaGetSymbolAddress((void**)&path, att_hi);
    cudaGetSymbolAddress((void**)&patl, att_lo);
    cudaGetSymbolAddress((void**)&pwqh, wqT_h);
    cudaGetSymbolAddress((void**)&pwql, wqT_l);
    cudaGetSymbolAddress((void**)&pwkh, wkT_h);
    cudaGetSymbolAddress((void**)&pwkl, wkT_l);
    cudaGetSymbolAddress((void**)&pwvh, wvT_h);
    cudaGetSymbolAddress((void**)&pwvl, wvT_l);
    cudaGetSymbolAddress((void**)&pwoh, woT_h);
    cudaGetSymbolAddress((void**)&pwol, woT_l);

    cudaFuncSetAttribute(gemm_hmma, cudaFuncAttributeMaxDynamicSharedMemorySize, GH_SMEM);
    cudaFuncSetAttribute(attn_flash, cudaFuncAttributeMaxDynamicSharedMemorySize, FA_SMEM);

    // Split x; transpose+split weights
    convert_x<<<(SEQ * DMODEL / 4) / 256, 256>>>(x);
    transpose_w<<<dim3(DMODEL / 32, DMODEL / 32), dim3(32, 8)>>>(wq, pwqh, pwql, DMODEL);
    transpose_w<<<dim3(1024 / 32, DMODEL / 32), dim3(32, 8)>>>(wk, pwkh, pwkl, 1024);
    transpose_w<<<dim3(1024 / 32, DMODEL / 32), dim3(32, 8)>>>(wv, pwvh, pwvl, 1024);
    transpose_w<<<dim3(DMODEL / 32, DMODEL / 32), dim3(32, 8)>>>(wo, pwoh, pwol, DMODEL);

    // QKV projections (HMMA)
    gemm_hmma<<<dim3(DMODEL / 128, SEQ / 128), 256, GH_SMEM>>>(pah, pal, pwqh, pwql, gq, DMODEL);
    gemm_hmma<<<dim3(1024 / 128, SEQ / 128), 256, GH_SMEM>>>(pah, pal, pwkh, pwkl, gk, 1024);
    gemm_hmma<<<dim3(1024 / 128, SEQ / 128), 256, GH_SMEM>>>(pah, pal, pwvh, pwvl, gv, 1024);

    // RoPE + fp16 conversions
    {
        int np = SEQ * (NHEAD + NKVH + NKVH) * 64;
        rope_conv<<<(np + 255) / 256, 256>>>(fcos, fsin);
    }

    // Flash attention (HMMA, register softmax)
    attn_flash<<<dim3(SEQ / BQ, NHEAD), 256, FA_SMEM>>>();

    // Output projection (HMMA) -> d_out
    gemm_hmma<<<dim3(DMODEL / 128, SEQ / 128), 256, GH_SMEM>>>(path, patl, pwoh, pwol, out, DMODEL);
}